// round 7
// baseline (speedup 1.0000x reference)
#include <cuda_runtime.h>
#include <cuda_bf16.h>
#include <math.h>

// Problem dims (fixed)
#define B_  64
#define T_  512
#define E_  256
#define H_  256
#define O_  256
#define M_  (T_ * B_)          // 32768 rows (t-major, b-minor)

// Scan W_hh split: 192 rows (96 f32x2 pairs) in registers, 64 rows in shared (paired)
#define KREGP 96               // register pairs   (k = 0..191)
#define KSH2  16               // shared ulonglong2 groups of 4 rows (k = 192..255)
#define SMEM_SCAN ((2 * H_) * sizeof(float) + (KSH2 * H_) * sizeof(ulonglong2))

// x prefetch depth (register ring)
#define XPF 4

typedef unsigned long long u64;

// ---------------------------------------------------------------------------
// f32x2 packed-FMA helpers (sm_100a)
// ---------------------------------------------------------------------------
__device__ __forceinline__ u64 pk2(float lo, float hi) {
    u64 r;
    asm("mov.b64 %0, {%1, %2};" : "=l"(r) : "f"(lo), "f"(hi));
    return r;
}
__device__ __forceinline__ void upk2(u64 v, float& lo, float& hi) {
    asm("mov.b64 {%0, %1}, %2;" : "=f"(lo), "=f"(hi) : "l"(v));
}
#define FMA2(d, a, b, c) \
    asm("fma.rn.f32x2 %0, %1, %2, %3;" : "=l"(d) : "l"(a), "l"(b), "l"(c))

__device__ __forceinline__ float fast_tanh(float v) {
    float x = fminf(fmaxf(v, -15.f), 15.f);
    float e = __expf(2.f * x);
    return __fdividef(e - 1.f, e + 1.f);
}

// dup-B swizzle: column c -> u64 slot (c%4)*16 + (c/4)   (c in 0..63)
#define BSLOT(c) (((c) & 3) * 16 + ((c) >> 2))

// ---------------------------------------------------------------------------
// Static device scratch (no allocation allowed)
// ---------------------------------------------------------------------------
__device__ float g_xf[(size_t)T_ * B_ * H_];   // xf[t][b][j]   (32 MB)
__device__ float g_xb[(size_t)T_ * B_ * H_];   // xb[s][b][j], s = scan index (32 MB)
__device__ float g_h [(size_t)M_ * (2 * H_)];  // hcat[t*64+b][0:256]=hf, [256:512]=hb (64 MB)

// ---------------------------------------------------------------------------
// Kernel 1: fused input projections. Zero-MOV inner loop:
// A as natural u64 pairs, B pre-duplicated {w,w} in SWIZZLED smem layout
// (reads for fixed j are 16 consecutive u64 -> conflict-free).
// ---------------------------------------------------------------------------
__global__ __launch_bounds__(256) void proj_kernel(
    const float* __restrict__ X,
    const float* __restrict__ Wf, const float* __restrict__ bfv,
    const float* __restrict__ Wb, const float* __restrict__ bbv)
{
    __shared__ float As [16][132];   // [k][m], padded
    __shared__ u64  Bfs2[16][64];    // [k][slot] pre-dup swizzled
    __shared__ u64  Bbs2[16][64];

    const int tid = threadIdx.x;
    const int m0 = blockIdx.y * 128;
    const int j0 = blockIdx.x * 64;

    const int rbase = (tid >> 4) * 8;     // 0..120
    const int cbase = (tid & 15) * 4;     // 0..60
    const int lane16 = tid & 15;

    const int lr = tid >> 1;              // 0..127
    const int lc = (tid & 1) * 8;         // 0 or 8
    const int gm = m0 + lr;
    const float* arow = X + ((size_t)(gm & 63) * T_ + (gm >> 6)) * E_;

    const int bk = tid >> 4;              // 0..15
    const int bj = (tid & 15) * 4;        // 0..60

    u64 accf2[4][4], accb2[4][4];
    const u64 z2 = pk2(0.f, 0.f);
#pragma unroll
    for (int i = 0; i < 4; i++)
#pragma unroll
        for (int j = 0; j < 4; j++) { accf2[i][j] = z2; accb2[i][j] = z2; }

    for (int e0 = 0; e0 < E_; e0 += 16) {
        float4 a0 = *(const float4*)(arow + e0 + lc);
        float4 a1 = *(const float4*)(arow + e0 + lc + 4);
        float4 f4 = *(const float4*)(Wf + (size_t)(e0 + bk) * H_ + j0 + bj);
        float4 b4 = *(const float4*)(Wb + (size_t)(e0 + bk) * H_ + j0 + bj);
        __syncthreads();
        As[lc + 0][lr] = a0.x; As[lc + 1][lr] = a0.y;
        As[lc + 2][lr] = a0.z; As[lc + 3][lr] = a0.w;
        As[lc + 4][lr] = a1.x; As[lc + 5][lr] = a1.y;
        As[lc + 6][lr] = a1.z; As[lc + 7][lr] = a1.w;
        // bj = (tid&15)*4, so c = bj + j with c%4 == j, c/4 == (tid&15)
        Bfs2[bk][BSLOT(bj + 0)] = pk2(f4.x, f4.x);
        Bfs2[bk][BSLOT(bj + 1)] = pk2(f4.y, f4.y);
        Bfs2[bk][BSLOT(bj + 2)] = pk2(f4.z, f4.z);
        Bfs2[bk][BSLOT(bj + 3)] = pk2(f4.w, f4.w);
        Bbs2[bk][BSLOT(bj + 0)] = pk2(b4.x, b4.x);
        Bbs2[bk][BSLOT(bj + 1)] = pk2(b4.y, b4.y);
        Bbs2[bk][BSLOT(bj + 2)] = pk2(b4.z, b4.z);
        Bbs2[bk][BSLOT(bj + 3)] = pk2(b4.w, b4.w);
        __syncthreads();
#pragma unroll
        for (int kk = 0; kk < 16; kk++) {
            u64 a2[4], f2[4], b2[4];
#pragma unroll
            for (int i2 = 0; i2 < 4; i2++)
                a2[i2] = *(const u64*)&As[kk][rbase + 2 * i2];
#pragma unroll
            for (int j = 0; j < 4; j++) {
                f2[j] = Bfs2[kk][j * 16 + lane16];   // == BSLOT(cbase + j)
                b2[j] = Bbs2[kk][j * 16 + lane16];
            }
#pragma unroll
            for (int i2 = 0; i2 < 4; i2++)
#pragma unroll
                for (int j = 0; j < 4; j++) {
                    FMA2(accf2[i2][j], a2[i2], f2[j], accf2[i2][j]);
                    FMA2(accb2[i2][j], a2[i2], b2[j], accb2[i2][j]);
                }
        }
    }

    float acc_f[8][4], acc_b[8][4];
#pragma unroll
    for (int i2 = 0; i2 < 4; i2++)
#pragma unroll
        for (int j = 0; j < 4; j++) {
            upk2(accf2[i2][j], acc_f[2 * i2][j], acc_f[2 * i2 + 1][j]);
            upk2(accb2[i2][j], acc_b[2 * i2][j], acc_b[2 * i2 + 1][j]);
        }

#pragma unroll
    for (int i = 0; i < 8; i++) {
        const int m = m0 + rbase + i;
        const int t = m >> 6, b = m & 63;
        const int m2 = (T_ - 1 - t) * B_ + b;      // scan index slot for xb
        float4 vf, vb;
        vf.x = acc_f[i][0] + bfv[j0 + cbase + 0];
        vf.y = acc_f[i][1] + bfv[j0 + cbase + 1];
        vf.z = acc_f[i][2] + bfv[j0 + cbase + 2];
        vf.w = acc_f[i][3] + bfv[j0 + cbase + 3];
        vb.x = acc_b[i][0] + bbv[j0 + cbase + 0];
        vb.y = acc_b[i][1] + bbv[j0 + cbase + 1];
        vb.z = acc_b[i][2] + bbv[j0 + cbase + 2];
        vb.w = acc_b[i][3] + bbv[j0 + cbase + 3];
        *(float4*)&g_xf[(size_t)m  * H_ + j0 + cbase] = vf;
        *(float4*)&g_xb[(size_t)m2 * H_ + j0 + cbase] = vb;
    }
}

// ---------------------------------------------------------------------------
// Kernel 2: persistent recurrent scan. 192 W rows in registers (96 pairs),
// 64 rows in shared -> smem crossbar 96KB->64KB per step.
// Deep x prefetch ring, zero-MOV FFMA2 inner loop.
// ---------------------------------------------------------------------------
extern __shared__ float smem_scan[];

__global__ __launch_bounds__(256) void scan_kernel(
    const float* __restrict__ Whh_f,
    const float* __restrict__ Whh_b,
    float* __restrict__ out)
{
    float*      h_sh = smem_scan;                         // [2][256]
    ulonglong2* Wsh2 = (ulonglong2*)(smem_scan + 2 * H_); // [KSH2][256]

    const int t   = threadIdx.x;
    const int dir = blockIdx.x >> 6;    // 0 = fwd, 1 = bwd
    const int b   = blockIdx.x & 63;

    const float* W    = dir ? Whh_b : Whh_f;
    const float* xarr = dir ? g_xb  : g_xf;

    // register W pairs: wreg[p] = {W[2p][t], W[2p+1][t]}, k = 0..191
    u64 wreg[KREGP];
#pragma unroll
    for (int p = 0; p < KREGP; p++)
        wreg[p] = pk2(W[(size_t)(2 * p) * H_ + t], W[(size_t)(2 * p + 1) * H_ + t]);
    // shared W tail, pre-paired (lane-consecutive -> conflict-free), k = 192..255
    for (int r = 0; r < KSH2; r++) {
        ulonglong2 w;
        w.x = pk2(W[(size_t)(2 * KREGP + 4 * r + 0) * H_ + t], W[(size_t)(2 * KREGP + 4 * r + 1) * H_ + t]);
        w.y = pk2(W[(size_t)(2 * KREGP + 4 * r + 2) * H_ + t], W[(size_t)(2 * KREGP + 4 * r + 3) * H_ + t]);
        Wsh2[r * H_ + t] = w;
    }
    h_sh[t] = 0.f;
    __syncthreads();

    const float* xp = xarr + (size_t)b * H_ + t;  // step stride = B_*H_

    // x prefetch ring: xq[i] holds x for step s+i
    float xq[XPF];
#pragma unroll
    for (int i = 0; i < XPF; i++)
        xq[i] = (i < T_) ? xp[(size_t)i * (B_ * H_)] : 0.f;

    float hlast = 0.f;
    int p = 0;

    const u64 z2 = pk2(0.f, 0.f);

    for (int s = 0; s < T_; ++s) {
        float x_cur = xq[0];
#pragma unroll
        for (int i = 0; i < XPF - 1; i++) xq[i] = xq[i + 1];
        if (s + XPF < T_) xq[XPF - 1] = xp[(size_t)(s + XPF) * (B_ * H_)];

        const ulonglong2* hc2 = (const ulonglong2*)(h_sh + p * H_); // 16B-aligned
        u64 a0 = z2, a1 = z2, a2 = z2, a3 = z2;

        // register-resident W rows: k = 0..191 (48 broadcast LDS.128)
#pragma unroll
        for (int q = 0; q < 2 * KREGP / 4; q++) {
            ulonglong2 hv = hc2[q];
            if (q & 1) {
                FMA2(a2, hv.x, wreg[2 * q + 0], a2);
                FMA2(a3, hv.y, wreg[2 * q + 1], a3);
            } else {
                FMA2(a0, hv.x, wreg[2 * q + 0], a0);
                FMA2(a1, hv.y, wreg[2 * q + 1], a1);
            }
        }
        // shared-resident W rows: k = 192..255
#pragma unroll
        for (int r = 0; r < KSH2; r++) {
            ulonglong2 hv = hc2[2 * KREGP / 4 + r];
            ulonglong2 wv = Wsh2[r * H_ + t];
            FMA2(a0, hv.x, wv.x, a0);
            FMA2(a1, hv.y, wv.y, a1);
        }

        float l0, u0, l1, u1, l2, u2, l3, u3;
        upk2(a0, l0, u0); upk2(a1, l1, u1);
        upk2(a2, l2, u2); upk2(a3, l3, u3);
        float sum = ((l0 + u0) + (l1 + u1)) + ((l2 + u2) + (l3 + u3)) + x_cur;
        float hn = fast_tanh(sum);

        h_sh[(p ^ 1) * H_ + t] = hn;

        const int t_orig = dir ? (T_ - 1 - s) : s;
        g_h[((size_t)(t_orig * B_ + b)) * (2 * H_) + dir * H_ + t] = hn;

        hlast = hn;
        p ^= 1;
        __syncthreads();
    }

    out[(size_t)B_ * T_ * O_ + (size_t)dir * (B_ * H_) + (size_t)b * H_ + t] = hlast;
}

// ---------------------------------------------------------------------------
// Kernel 3: output GEMM. Same swizzled dup-B scheme as proj.
// ---------------------------------------------------------------------------
__global__ __launch_bounds__(256) void out_kernel(
    const float* __restrict__ Why, const float* __restrict__ byv,
    float* __restrict__ out)
{
    __shared__ float As[16][132];
    __shared__ u64  Bs2[16][64];

    const int tid = threadIdx.x;
    const int m0 = blockIdx.y * 128;
    const int j0 = blockIdx.x * 64;

    const int rbase = (tid >> 4) * 8;
    const int cbase = (tid & 15) * 4;
    const int lane16 = tid & 15;

    const int lr = tid >> 1;
    const int lc = (tid & 1) * 8;
    const float* arow = g_h + (size_t)(m0 + lr) * (2 * H_);

    const int bk = tid >> 4;
    const int bj = (tid & 15) * 4;

    u64 acc2[4][4];
    const u64 z2 = pk2(0.f, 0.f);
#pragma unroll
    for (int i = 0; i < 4; i++)
#pragma unroll
        for (int j = 0; j < 4; j++) acc2[i][j] = z2;

    for (int e0 = 0; e0 < 2 * H_; e0 += 16) {
        float4 a0 = *(const float4*)(arow + e0 + lc);
        float4 a1 = *(const float4*)(arow + e0 + lc + 4);
        float4 w4 = *(const float4*)(Why + (size_t)(e0 + bk) * O_ + j0 + bj);
        __syncthreads();
        As[lc + 0][lr] = a0.x; As[lc + 1][lr] = a0.y;
        As[lc + 2][lr] = a0.z; As[lc + 3][lr] = a0.w;
        As[lc + 4][lr] = a1.x; As[lc + 5][lr] = a1.y;
        As[lc + 6][lr] = a1.z; As[lc + 7][lr] = a1.w;
        Bs2[bk][BSLOT(bj + 0)] = pk2(w4.x, w4.x);
        Bs2[bk][BSLOT(bj + 1)] = pk2(w4.y, w4.y);
        Bs2[bk][BSLOT(bj + 2)] = pk2(w4.z, w4.z);
        Bs2[bk][BSLOT(bj + 3)] = pk2(w4.w, w4.w);
        __syncthreads();
#pragma unroll
        for (int kk = 0; kk < 16; kk++) {
            u64 a2[4], w2[4];
#pragma unroll
            for (int i2 = 0; i2 < 4; i2++)
                a2[i2] = *(const u64*)&As[kk][rbase + 2 * i2];
#pragma unroll
            for (int j = 0; j < 4; j++)
                w2[j] = Bs2[kk][j * 16 + lane16];
#pragma unroll
            for (int i2 = 0; i2 < 4; i2++)
#pragma unroll
                for (int j = 0; j < 4; j++)
                    FMA2(acc2[i2][j], a2[i2], w2[j], acc2[i2][j]);
        }
    }

    float acc[8][4];
#pragma unroll
    for (int i2 = 0; i2 < 4; i2++)
#pragma unroll
        for (int j = 0; j < 4; j++)
            upk2(acc2[i2][j], acc[2 * i2][j], acc[2 * i2 + 1][j]);

#pragma unroll
    for (int i = 0; i < 8; i++) {
        const int m = m0 + rbase + i;
        const int t = m >> 6, b = m & 63;
        float4 v;
        v.x = acc[i][0] + byv[j0 + cbase + 0];
        v.y = acc[i][1] + byv[j0 + cbase + 1];
        v.z = acc[i][2] + byv[j0 + cbase + 2];
        v.w = acc[i][3] + byv[j0 + cbase + 3];
        *(float4*)&out[((size_t)b * T_ + t) * O_ + j0 + cbase] = v;
    }
}

// ---------------------------------------------------------------------------
// launch
// ---------------------------------------------------------------------------
extern "C" void kernel_launch(void* const* d_in, const int* in_sizes, int n_in,
                              void* d_out, int out_size)
{
    const float* X    = (const float*)d_in[0];
    const float* Wxhf = (const float*)d_in[1];
    const float* Whhf = (const float*)d_in[2];
    const float* bf   = (const float*)d_in[3];
    const float* Wxhb = (const float*)d_in[4];
    const float* Whhb = (const float*)d_in[5];
    const float* bb   = (const float*)d_in[6];
    const float* Why  = (const float*)d_in[7];
    const float* by   = (const float*)d_in[8];
    float* out = (float*)d_out;

    cudaFuncSetAttribute(scan_kernel,
                         cudaFuncAttributeMaxDynamicSharedMemorySize,
                         (int)SMEM_SCAN);

    proj_kernel<<<dim3(4, 256), 256>>>(X, Wxhf, bf, Wxhb, bb);
    scan_kernel<<<128, 256, SMEM_SCAN>>>(Whhf, Whhb, out);
    out_kernel<<<dim3(4, 256), 256>>>(Why, by, out);
}

// round 8
// speedup vs baseline: 1.1243x; 1.1243x over previous
#include <cuda_runtime.h>
#include <cuda_bf16.h>
#include <math.h>

// Problem dims (fixed)
#define B_  64
#define T_  512
#define E_  256
#define H_  256
#define O_  256
#define M_  (T_ * B_)          // 32768 rows (t-major, b-minor)

// Scan W_hh split: 200 rows (100 f32x2 pairs) in registers, 56 rows in shared (paired)
#define KREGP 100              // register pairs   (k = 0..199)
#define KSH2  14               // shared ulonglong2 groups of 4 rows (k = 200..255)
#define SMEM_SCAN ((2 * H_) * sizeof(float) + (KSH2 * H_) * sizeof(ulonglong2))

// x prefetch depth (register ring)
#define XPF 4

typedef unsigned long long u64;

// ---------------------------------------------------------------------------
// f32x2 packed-FMA helpers (sm_100a)
// ---------------------------------------------------------------------------
__device__ __forceinline__ u64 pk2(float lo, float hi) {
    u64 r;
    asm("mov.b64 %0, {%1, %2};" : "=l"(r) : "f"(lo), "f"(hi));
    return r;
}
__device__ __forceinline__ void upk2(u64 v, float& lo, float& hi) {
    asm("mov.b64 {%0, %1}, %2;" : "=f"(lo), "=f"(hi) : "l"(v));
}
#define FMA2(d, a, b, c) \
    asm("fma.rn.f32x2 %0, %1, %2, %3;" : "=l"(d) : "l"(a), "l"(b), "l"(c))

__device__ __forceinline__ float fast_tanh(float v) {
    float x = fminf(fmaxf(v, -15.f), 15.f);
    float e = __expf(2.f * x);
    return __fdividef(e - 1.f, e + 1.f);
}

// ---------------------------------------------------------------------------
// Static device scratch (no allocation allowed)
// ---------------------------------------------------------------------------
__device__ float g_xf[(size_t)T_ * B_ * H_];   // xf[t][b][j]   (32 MB)
__device__ float g_xb[(size_t)T_ * B_ * H_];   // xb[s][b][j], s = scan index (32 MB)
__device__ float g_h [(size_t)M_ * (2 * H_)];  // hcat[t*64+b][0:256]=hf, [256:512]=hb (64 MB)

// ---------------------------------------------------------------------------
// Kernel 1: fused input projections (R6 version — best measured 189us).
// FFMA2 with float4 B loads + register dup-packs, natural A pairs.
// ---------------------------------------------------------------------------
__global__ __launch_bounds__(256) void proj_kernel(
    const float* __restrict__ X,
    const float* __restrict__ Wf, const float* __restrict__ bfv,
    const float* __restrict__ Wb, const float* __restrict__ bbv)
{
    __shared__ float As [16][132];  // [k][m], padded
    __shared__ float Bfs[16][68];   // [k][j], padded
    __shared__ float Bbs[16][68];

    const int tid = threadIdx.x;
    const int m0 = blockIdx.y * 128;
    const int j0 = blockIdx.x * 64;

    const int rbase = (tid >> 4) * 8;     // 0..120
    const int cbase = (tid & 15) * 4;     // 0..60

    const int lr = tid >> 1;              // 0..127
    const int lc = (tid & 1) * 8;         // 0 or 8
    const int gm = m0 + lr;
    const float* arow = X + ((size_t)(gm & 63) * T_ + (gm >> 6)) * E_;

    const int bk = tid >> 4;              // 0..15
    const int bj = (tid & 15) * 4;        // 0..60

    u64 accf2[4][4], accb2[4][4];
    const u64 z2 = pk2(0.f, 0.f);
#pragma unroll
    for (int i = 0; i < 4; i++)
#pragma unroll
        for (int j = 0; j < 4; j++) { accf2[i][j] = z2; accb2[i][j] = z2; }

    for (int e0 = 0; e0 < E_; e0 += 16) {
        float4 a0 = *(const float4*)(arow + e0 + lc);
        float4 a1 = *(const float4*)(arow + e0 + lc + 4);
        float4 f4 = *(const float4*)(Wf + (size_t)(e0 + bk) * H_ + j0 + bj);
        float4 b4 = *(const float4*)(Wb + (size_t)(e0 + bk) * H_ + j0 + bj);
        __syncthreads();
        As[lc + 0][lr] = a0.x; As[lc + 1][lr] = a0.y;
        As[lc + 2][lr] = a0.z; As[lc + 3][lr] = a0.w;
        As[lc + 4][lr] = a1.x; As[lc + 5][lr] = a1.y;
        As[lc + 6][lr] = a1.z; As[lc + 7][lr] = a1.w;
        *(float4*)&Bfs[bk][bj] = f4;
        *(float4*)&Bbs[bk][bj] = b4;
        __syncthreads();
#pragma unroll
        for (int kk = 0; kk < 16; kk++) {
            u64 a2[4];
#pragma unroll
            for (int i2 = 0; i2 < 4; i2++) {
                float2 av = *(const float2*)&As[kk][rbase + 2 * i2];
                a2[i2] = pk2(av.x, av.y);
            }
            float4 fv = *(const float4*)&Bfs[kk][cbase];
            float4 bv = *(const float4*)&Bbs[kk][cbase];
            u64 f2[4], b2[4];
            f2[0] = pk2(fv.x, fv.x); f2[1] = pk2(fv.y, fv.y);
            f2[2] = pk2(fv.z, fv.z); f2[3] = pk2(fv.w, fv.w);
            b2[0] = pk2(bv.x, bv.x); b2[1] = pk2(bv.y, bv.y);
            b2[2] = pk2(bv.z, bv.z); b2[3] = pk2(bv.w, bv.w);
#pragma unroll
            for (int i2 = 0; i2 < 4; i2++)
#pragma unroll
                for (int j = 0; j < 4; j++) {
                    FMA2(accf2[i2][j], a2[i2], f2[j], accf2[i2][j]);
                    FMA2(accb2[i2][j], a2[i2], b2[j], accb2[i2][j]);
                }
        }
    }

    float acc_f[8][4], acc_b[8][4];
#pragma unroll
    for (int i2 = 0; i2 < 4; i2++)
#pragma unroll
        for (int j = 0; j < 4; j++) {
            upk2(accf2[i2][j], acc_f[2 * i2][j], acc_f[2 * i2 + 1][j]);
            upk2(accb2[i2][j], acc_b[2 * i2][j], acc_b[2 * i2 + 1][j]);
        }

#pragma unroll
    for (int i = 0; i < 8; i++) {
        const int m = m0 + rbase + i;
        const int t = m >> 6, b = m & 63;
        const int m2 = (T_ - 1 - t) * B_ + b;      // scan index slot for xb
        float4 vf, vb;
        vf.x = acc_f[i][0] + bfv[j0 + cbase + 0];
        vf.y = acc_f[i][1] + bfv[j0 + cbase + 1];
        vf.z = acc_f[i][2] + bfv[j0 + cbase + 2];
        vf.w = acc_f[i][3] + bfv[j0 + cbase + 3];
        vb.x = acc_b[i][0] + bbv[j0 + cbase + 0];
        vb.y = acc_b[i][1] + bbv[j0 + cbase + 1];
        vb.z = acc_b[i][2] + bbv[j0 + cbase + 2];
        vb.w = acc_b[i][3] + bbv[j0 + cbase + 3];
        *(float4*)&g_xf[(size_t)m  * H_ + j0 + cbase] = vf;
        *(float4*)&g_xb[(size_t)m2 * H_ + j0 + cbase] = vb;
    }
}

// ---------------------------------------------------------------------------
// Kernel 2: persistent recurrent scan. 200 W rows in registers (100 pairs),
// 56 rows in shared -> crossbar 56KB/step. Deep x prefetch, x folded into
// accumulator init, incremental g_h store pointer.
// ---------------------------------------------------------------------------
extern __shared__ float smem_scan[];

__global__ __launch_bounds__(256) void scan_kernel(
    const float* __restrict__ Whh_f,
    const float* __restrict__ Whh_b,
    float* __restrict__ out)
{
    float*      h_sh = smem_scan;                         // [2][256]
    ulonglong2* Wsh2 = (ulonglong2*)(smem_scan + 2 * H_); // [KSH2][256]

    const int t   = threadIdx.x;
    const int dir = blockIdx.x >> 6;    // 0 = fwd, 1 = bwd
    const int b   = blockIdx.x & 63;

    const float* W    = dir ? Whh_b : Whh_f;
    const float* xarr = dir ? g_xb  : g_xf;

    // register W pairs: wreg[p] = {W[2p][t], W[2p+1][t]}, k = 0..199
    u64 wreg[KREGP];
#pragma unroll
    for (int p = 0; p < KREGP; p++)
        wreg[p] = pk2(W[(size_t)(2 * p) * H_ + t], W[(size_t)(2 * p + 1) * H_ + t]);
    // shared W tail, pre-paired (lane-consecutive -> conflict-free), k = 200..255
    for (int r = 0; r < KSH2; r++) {
        ulonglong2 w;
        w.x = pk2(W[(size_t)(2 * KREGP + 4 * r + 0) * H_ + t], W[(size_t)(2 * KREGP + 4 * r + 1) * H_ + t]);
        w.y = pk2(W[(size_t)(2 * KREGP + 4 * r + 2) * H_ + t], W[(size_t)(2 * KREGP + 4 * r + 3) * H_ + t]);
        Wsh2[r * H_ + t] = w;
    }
    h_sh[t] = 0.f;
    __syncthreads();

    const float* xp = xarr + (size_t)b * H_ + t;  // step stride = B_*H_

    // incremental g_h store pointer: dir 0 starts at t_orig=0 and walks +,
    // dir 1 starts at t_orig=T-1 and walks -.
    float* ghp = g_h + ((size_t)((dir ? (T_ - 1) : 0) * B_ + b)) * (2 * H_) + dir * H_ + t;
    const long long gstep = dir ? -(long long)(B_ * 2 * H_) : (long long)(B_ * 2 * H_);

    // x prefetch ring: xq[i] holds x for step s+i
    float xq[XPF];
#pragma unroll
    for (int i = 0; i < XPF; i++)
        xq[i] = (i < T_) ? xp[(size_t)i * (B_ * H_)] : 0.f;

    float hlast = 0.f;
    int p = 0;

    const u64 z2 = pk2(0.f, 0.f);

    for (int s = 0; s < T_; ++s) {
        // fold x into a0's low lane at init (saves a dependent add at the end)
        u64 a0 = pk2(xq[0], 0.f), a1 = z2, a2 = z2, a3 = z2;
#pragma unroll
        for (int i = 0; i < XPF - 1; i++) xq[i] = xq[i + 1];
        if (s + XPF < T_) xq[XPF - 1] = xp[(size_t)(s + XPF) * (B_ * H_)];

        const ulonglong2* hc2 = (const ulonglong2*)(h_sh + p * H_); // 16B-aligned

        // register-resident W rows: k = 0..199 (50 broadcast LDS.128)
#pragma unroll
        for (int q = 0; q < 2 * KREGP / 4; q++) {
            ulonglong2 hv = hc2[q];
            if (q & 1) {
                FMA2(a2, hv.x, wreg[2 * q + 0], a2);
                FMA2(a3, hv.y, wreg[2 * q + 1], a3);
            } else {
                FMA2(a0, hv.x, wreg[2 * q + 0], a0);
                FMA2(a1, hv.y, wreg[2 * q + 1], a1);
            }
        }
        // shared-resident W rows: k = 200..255
#pragma unroll
        for (int r = 0; r < KSH2; r++) {
            ulonglong2 hv = hc2[2 * KREGP / 4 + r];
            ulonglong2 wv = Wsh2[r * H_ + t];
            FMA2(a0, hv.x, wv.x, a0);
            FMA2(a1, hv.y, wv.y, a1);
        }

        float l0, u0, l1, u1, l2, u2, l3, u3;
        upk2(a0, l0, u0); upk2(a1, l1, u1);
        upk2(a2, l2, u2); upk2(a3, l3, u3);
        float sum = ((l0 + u0) + (l1 + u1)) + ((l2 + u2) + (l3 + u3));
        float hn = fast_tanh(sum);

        h_sh[(p ^ 1) * H_ + t] = hn;
        *ghp = hn;
        ghp += gstep;

        hlast = hn;
        p ^= 1;
        __syncthreads();
    }

    out[(size_t)B_ * T_ * O_ + (size_t)dir * (B_ * H_) + (size_t)b * H_ + t] = hlast;
}

// ---------------------------------------------------------------------------
// Kernel 3: output GEMM (R6 version — float4 B loads + register dup-packs).
// ---------------------------------------------------------------------------
__global__ __launch_bounds__(256) void out_kernel(
    const float* __restrict__ Why, const float* __restrict__ byv,
    float* __restrict__ out)
{
    __shared__ float As[16][132];
    __shared__ float Bs[16][68];

    const int tid = threadIdx.x;
    const int m0 = blockIdx.y * 128;
    const int j0 = blockIdx.x * 64;

    const int rbase = (tid >> 4) * 8;
    const int cbase = (tid & 15) * 4;

    const int lr = tid >> 1;
    const int lc = (tid & 1) * 8;
    const float* arow = g_h + (size_t)(m0 + lr) * (2 * H_);

    const int bk = tid >> 4;
    const int bj = (tid & 15) * 4;

    u64 acc2[4][4];
    const u64 z2 = pk2(0.f, 0.f);
#pragma unroll
    for (int i = 0; i < 4; i++)
#pragma unroll
        for (int j = 0; j < 4; j++) acc2[i][j] = z2;

    for (int e0 = 0; e0 < 2 * H_; e0 += 16) {
        float4 a0 = *(const float4*)(arow + e0 + lc);
        float4 a1 = *(const float4*)(arow + e0 + lc + 4);
        float4 w4 = *(const float4*)(Why + (size_t)(e0 + bk) * O_ + j0 + bj);
        __syncthreads();
        As[lc + 0][lr] = a0.x; As[lc + 1][lr] = a0.y;
        As[lc + 2][lr] = a0.z; As[lc + 3][lr] = a0.w;
        As[lc + 4][lr] = a1.x; As[lc + 5][lr] = a1.y;
        As[lc + 6][lr] = a1.z; As[lc + 7][lr] = a1.w;
        *(float4*)&Bs[bk][bj] = w4;
        __syncthreads();
#pragma unroll
        for (int kk = 0; kk < 16; kk++) {
            u64 a2[4];
#pragma unroll
            for (int i2 = 0; i2 < 4; i2++) {
                float2 av = *(const float2*)&As[kk][rbase + 2 * i2];
                a2[i2] = pk2(av.x, av.y);
            }
            float4 wv = *(const float4*)&Bs[kk][cbase];
            u64 w2[4];
            w2[0] = pk2(wv.x, wv.x); w2[1] = pk2(wv.y, wv.y);
            w2[2] = pk2(wv.z, wv.z); w2[3] = pk2(wv.w, wv.w);
#pragma unroll
            for (int i2 = 0; i2 < 4; i2++)
#pragma unroll
                for (int j = 0; j < 4; j++)
                    FMA2(acc2[i2][j], a2[i2], w2[j], acc2[i2][j]);
        }
    }

    float acc[8][4];
#pragma unroll
    for (int i2 = 0; i2 < 4; i2++)
#pragma unroll
        for (int j = 0; j < 4; j++)
            upk2(acc2[i2][j], acc[2 * i2][j], acc[2 * i2 + 1][j]);

#pragma unroll
    for (int i = 0; i < 8; i++) {
        const int m = m0 + rbase + i;
        const int t = m >> 6, b = m & 63;
        float4 v;
        v.x = acc[i][0] + byv[j0 + cbase + 0];
        v.y = acc[i][1] + byv[j0 + cbase + 1];
        v.z = acc[i][2] + byv[j0 + cbase + 2];
        v.w = acc[i][3] + byv[j0 + cbase + 3];
        *(float4*)&out[((size_t)b * T_ + t) * O_ + j0 + cbase] = v;
    }
}

// ---------------------------------------------------------------------------
// launch
// ---------------------------------------------------------------------------
extern "C" void kernel_launch(void* const* d_in, const int* in_sizes, int n_in,
                              void* d_out, int out_size)
{
    const float* X    = (const float*)d_in[0];
    const float* Wxhf = (const float*)d_in[1];
    const float* Whhf = (const float*)d_in[2];
    const float* bf   = (const float*)d_in[3];
    const float* Wxhb = (const float*)d_in[4];
    const float* Whhb = (const float*)d_in[5];
    const float* bb   = (const float*)d_in[6];
    const float* Why  = (const float*)d_in[7];
    const float* by   = (const float*)d_in[8];
    float* out = (float*)d_out;

    cudaFuncSetAttribute(scan_kernel,
                         cudaFuncAttributeMaxDynamicSharedMemorySize,
                         (int)SMEM_SCAN);

    proj_kernel<<<dim3(4, 256), 256>>>(X, Wxhf, bf, Wxhb, bb);
    scan_kernel<<<128, 256, SMEM_SCAN>>>(Whhf, Whhb, out);
    out_kernel<<<dim3(4, 256), 256>>>(Why, by, out);
}

// round 10
// speedup vs baseline: 1.1860x; 1.0549x over previous
#include <cuda_runtime.h>
#include <cuda_bf16.h>
#include <math.h>
#include <stdint.h>

// Problem dims (fixed)
#define B_  64
#define T_  512
#define E_  256
#define H_  256
#define O_  256
#define M_  (T_ * B_)          // 32768 rows

typedef unsigned long long u64;
typedef unsigned int u32;

// ---------------------------------------------------------------------------
// scan config (R8 winner, unchanged)
// ---------------------------------------------------------------------------
#define KREGP 100
#define KSH2  14
#define SMEM_SCAN ((2 * H_) * sizeof(float) + (KSH2 * H_) * sizeof(ulonglong2))
#define XPF 4

__device__ __forceinline__ u64 pk2(float lo, float hi) {
    u64 r;
    asm("mov.b64 %0, {%1, %2};" : "=l"(r) : "f"(lo), "f"(hi));
    return r;
}
__device__ __forceinline__ void upk2(u64 v, float& lo, float& hi) {
    asm("mov.b64 {%0, %1}, %2;" : "=f"(lo), "=f"(hi) : "l"(v));
}
#define FMA2(d, a, b, c) \
    asm("fma.rn.f32x2 %0, %1, %2, %3;" : "=l"(d) : "l"(a), "l"(b), "l"(c))

__device__ __forceinline__ float fast_tanh(float v) {
    float x = fminf(fmaxf(v, -15.f), 15.f);
    float e = __expf(2.f * x);
    return __fdividef(e - 1.f, e + 1.f);
}

// ---------------------------------------------------------------------------
// warp-mma helpers (legacy path, works on bare sm_100 target)
// ---------------------------------------------------------------------------
__device__ __forceinline__ u32 smem_u32(const void* p) {
    u32 a;
    asm("{ .reg .u64 t; cvta.to.shared.u64 t, %1; cvt.u32.u64 %0, t; }" : "=r"(a) : "l"(p));
    return a;
}
#define LDSM_X4(r, addr) \
    asm volatile("ldmatrix.sync.aligned.m8n8.x4.shared.b16 {%0,%1,%2,%3}, [%4];" \
        : "=r"((r)[0]), "=r"((r)[1]), "=r"((r)[2]), "=r"((r)[3]) : "r"(addr))
#define MMA_BF16(c, a, b0, b1) \
    asm volatile("mma.sync.aligned.m16n8k16.row.col.f32.bf16.bf16.f32 " \
        "{%0,%1,%2,%3}, {%4,%5,%6,%7}, {%8,%9}, {%0,%1,%2,%3};" \
        : "+f"((c)[0]), "+f"((c)[1]), "+f"((c)[2]), "+f"((c)[3]) \
        : "r"((a)[0]), "r"((a)[1]), "r"((a)[2]), "r"((a)[3]), "r"(b0), "r"(b1))

// ---------------------------------------------------------------------------
// Static device scratch
// ---------------------------------------------------------------------------
__device__ float g_xf[(size_t)T_ * B_ * H_];
__device__ float g_xb[(size_t)T_ * B_ * H_];
__device__ float g_h [(size_t)M_ * (2 * H_)];

// weights pre-split bf16 hi/lo, TRANSPOSED to [n][k] (k contiguous)
__device__ __nv_bfloat16 g_pBh[2 * H_ * E_];   // [dir][n][k], k = 0..255
__device__ __nv_bfloat16 g_pBl[2 * H_ * E_];
__device__ __nv_bfloat16 g_oBh[O_ * 2 * H_];   // [n][k], k = 0..511
__device__ __nv_bfloat16 g_oBl[O_ * 2 * H_];

// ---------------------------------------------------------------------------
// GEMM smem: A/B tiles, 128 rows x 64 bf16, rows padded to 144B (LDSM
// conflict-free: 8 row-addrs cover offsets 0,16,..,112 mod 128).
// ---------------------------------------------------------------------------
#define ROWB 144
#define SM_AH 0
#define SM_AL 18432
#define SM_BH 36864
#define SM_BL 55296
#define SMEM_TC 73728

__device__ __forceinline__ unsigned pkbf(float a, float b) {
    unsigned lo = __bfloat16_as_ushort(__float2bfloat16_rn(a));
    unsigned hi = __bfloat16_as_ushort(__float2bfloat16_rn(b));
    return (hi << 16) | lo;
}
__device__ __forceinline__ void cvt8(const float* v, uint4& Hq, uint4& Lq) {
    float fh[8], fl[8];
#pragma unroll
    for (int i = 0; i < 8; i++) {
        __nv_bfloat16 h = __float2bfloat16_rn(v[i]);
        fh[i] = __bfloat162float(h);
        fl[i] = v[i] - fh[i];
    }
    Hq.x = pkbf(fh[0], fh[1]); Hq.y = pkbf(fh[2], fh[3]);
    Hq.z = pkbf(fh[4], fh[5]); Hq.w = pkbf(fh[6], fh[7]);
    Lq.x = pkbf(fl[0], fl[1]); Lq.y = pkbf(fl[2], fl[3]);
    Lq.z = pkbf(fl[4], fl[5]); Lq.w = pkbf(fl[6], fl[7]);
}

// ---------------------------------------------------------------------------
// setup: split + transpose weights
// ---------------------------------------------------------------------------
__global__ void setup_kernel(const float* __restrict__ Wf,
                             const float* __restrict__ Wb,
                             const float* __restrict__ Why)
{
    const int stride = gridDim.x * blockDim.x;
    for (int e = blockIdx.x * blockDim.x + threadIdx.x; e < E_ * H_; e += stride) {
        int k = e >> 8, n = e & 255;          // W[k][n]
        int idx = n * E_ + k;                 // WT[n][k]
        float wf = Wf[e], wb = Wb[e];
        __nv_bfloat16 hf = __float2bfloat16_rn(wf);
        __nv_bfloat16 hb = __float2bfloat16_rn(wb);
        g_pBh[idx] = hf;
        g_pBl[idx] = __float2bfloat16_rn(wf - __bfloat162float(hf));
        g_pBh[H_ * E_ + idx] = hb;
        g_pBl[H_ * E_ + idx] = __float2bfloat16_rn(wb - __bfloat162float(hb));
    }
    for (int e = blockIdx.x * blockDim.x + threadIdx.x; e < 2 * H_ * O_; e += stride) {
        int k = e >> 8, n = e & 255;          // Why[k][n], k < 512
        int idx = n * (2 * H_) + k;
        float w = Why[e];
        __nv_bfloat16 h = __float2bfloat16_rn(w);
        g_oBh[idx] = h;
        g_oBl[idx] = __float2bfloat16_rn(w - __bfloat162float(h));
    }
}

// ---------------------------------------------------------------------------
// split-bf16 warp-MMA GEMM body: C[128 x 128] block tile, K = NKT*64.
// MODE 0: proj (A gathered from X, dst g_xf/g_xb);  MODE 1: out (A = g_h).
// ---------------------------------------------------------------------------
template <int NKT, int MODE>
__device__ __forceinline__ void gemm_mma_body(
    const float* __restrict__ Asrc,
    const __nv_bfloat16* __restrict__ Bh,
    const __nv_bfloat16* __restrict__ Bl,
    const float* __restrict__ bias,
    float* __restrict__ Cdst,
    int m0, int n0, int dir)
{
    extern __shared__ char smem[];
    const u32 smb = smem_u32(smem);
    const int tid = threadIdx.x;
    const int wid = tid >> 5;
    const int l   = tid & 31;
    const int wm  = wid & 1;       // 2 warp-rows of 64
    const int wn  = wid >> 1;      // 4 warp-cols of 32
    const int K   = NKT * 64;

    // A source row for the loader role (row r, k-half hf)
    const int r  = tid >> 1;
    const int hf = tid & 1;
    const float* arow;
    {
        const int m = m0 + r;
        if (MODE == 0) {
            int t = m >> 6, b = m & 63;
            int xt = dir ? (T_ - 1 - t) : t;
            arow = Asrc + ((size_t)b * T_ + xt) * E_;
        } else {
            arow = Asrc + (size_t)m * (2 * H_);
        }
    }
    // B loader role: arr (hi/lo), row rb
    const int barr = tid >> 7;
    const int rb   = tid & 127;
    const __nv_bfloat16* bsrc = (barr ? Bl : Bh) + (size_t)(n0 + rb) * K;
    char* bdst = smem + (barr ? SM_BL : SM_BH) + rb * ROWB;

    // LDSM per-lane base addresses
    u32 aAH[4], aAL[4];
#pragma unroll
    for (int f = 0; f < 4; f++) {
        u32 off = (u32)((wm * 64 + 16 * f + (l & 15)) * ROWB + (l >> 4) * 16);
        aAH[f] = smb + SM_AH + off;
        aAL[f] = smb + SM_AL + off;
    }
    u32 bBH[2], bBL[2];
#pragma unroll
    for (int p = 0; p < 2; p++) {
        u32 off = (u32)((wn * 32 + 16 * p + (l & 7) + (l >> 4) * 8) * ROWB + ((l >> 3) & 1) * 16);
        bBH[p] = smb + SM_BH + off;
        bBL[p] = smb + SM_BL + off;
    }

    float cc[4][4][4];
#pragma unroll
    for (int f = 0; f < 4; f++)
#pragma unroll
        for (int g = 0; g < 4; g++)
#pragma unroll
            for (int i = 0; i < 4; i++) cc[f][g][i] = 0.f;

    for (int kt = 0; kt < NKT; kt++) {
        // stage A (convert fp32 -> bf16 hi/lo) and B (flat copy)
        float av[32];
        const float* ap = arow + kt * 64 + hf * 32;
#pragma unroll
        for (int i = 0; i < 8; i++)
            *(float4*)&av[i * 4] = *(const float4*)(ap + i * 4);
        uint4 bq[8];
        const uint4* bs = (const uint4*)(bsrc + kt * 64);
#pragma unroll
        for (int i = 0; i < 8; i++) bq[i] = bs[i];

        if (kt > 0) __syncthreads();   // previous slab's LDSMs are done

#pragma unroll
        for (int c = 0; c < 4; c++) {
            uint4 Hq, Lq;
            cvt8(&av[c * 8], Hq, Lq);
            int off = r * ROWB + hf * 64 + c * 16;
            *(uint4*)(smem + SM_AH + off) = Hq;
            *(uint4*)(smem + SM_AL + off) = Lq;
        }
#pragma unroll
        for (int i = 0; i < 8; i++) *(uint4*)(bdst + i * 16) = bq[i];
        __syncthreads();

        // 4 k-steps of 16
#pragma unroll
        for (int ks = 0; ks < 4; ks++) {
            const u32 kb = ks * 32;
            u32 ah[4][4], al[4][4], bh2[2][4], bl2[2][4];
#pragma unroll
            for (int f = 0; f < 4; f++) { LDSM_X4(ah[f], aAH[f] + kb); LDSM_X4(al[f], aAL[f] + kb); }
#pragma unroll
            for (int p = 0; p < 2; p++) { LDSM_X4(bh2[p], bBH[p] + kb); LDSM_X4(bl2[p], bBL[p] + kb); }
#pragma unroll
            for (int f = 0; f < 4; f++)
#pragma unroll
                for (int g = 0; g < 4; g++) {
                    u32 h0 = bh2[g >> 1][(g & 1) * 2], h1 = bh2[g >> 1][(g & 1) * 2 + 1];
                    u32 l0 = bl2[g >> 1][(g & 1) * 2], l1 = bl2[g >> 1][(g & 1) * 2 + 1];
                    MMA_BF16(cc[f][g], ah[f], h0, h1);
                    MMA_BF16(cc[f][g], ah[f], l0, l1);
                    MMA_BF16(cc[f][g], al[f], h0, h1);
                }
        }
    }

    // epilogue: c-frag layout -> global, + bias
#pragma unroll
    for (int f = 0; f < 4; f++) {
        const int row0 = m0 + wm * 64 + 16 * f + (l >> 2);
#pragma unroll
        for (int g = 0; g < 4; g++) {
            const int col = n0 + wn * 32 + 8 * g + (l & 3) * 2;
            float2 bv = *(const float2*)(bias + col);
            float2 v0 = { cc[f][g][0] + bv.x, cc[f][g][1] + bv.y };
            float2 v1 = { cc[f][g][2] + bv.x, cc[f][g][3] + bv.y };
            if (MODE == 0) {
                *(float2*)(Cdst + (size_t)row0 * H_ + col) = v0;
                *(float2*)(Cdst + (size_t)(row0 + 8) * H_ + col) = v1;
            } else {
                int t0 = row0 >> 6, b0 = row0 & 63;
                int t1 = (row0 + 8) >> 6, b1 = (row0 + 8) & 63;
                *(float2*)(Cdst + ((size_t)b0 * T_ + t0) * O_ + col) = v0;
                *(float2*)(Cdst + ((size_t)b1 * T_ + t1) * O_ + col) = v1;
            }
        }
    }
}

__global__ __launch_bounds__(256, 1) void proj_tc(
    const float* __restrict__ X,
    const float* __restrict__ bfv, const float* __restrict__ bbv)
{
    const int dir = blockIdx.z;
    gemm_mma_body<4, 0>(X,
                        g_pBh + dir * (H_ * E_), g_pBl + dir * (H_ * E_),
                        dir ? bbv : bfv,
                        dir ? g_xb : g_xf,
                        blockIdx.x * 128, blockIdx.y * 128, dir);
}

__global__ __launch_bounds__(256, 1) void out_tc(
    const float* __restrict__ byv, float* __restrict__ out)
{
    gemm_mma_body<8, 1>(g_h, g_oBh, g_oBl, byv, out,
                        blockIdx.x * 128, blockIdx.y * 128, 0);
}

// ---------------------------------------------------------------------------
// scan kernel — EXACT R8 winner
// ---------------------------------------------------------------------------
extern __shared__ float smem_scan[];

__global__ __launch_bounds__(256) void scan_kernel(
    const float* __restrict__ Whh_f,
    const float* __restrict__ Whh_b,
    float* __restrict__ out)
{
    float*      h_sh = smem_scan;
    ulonglong2* Wsh2 = (ulonglong2*)(smem_scan + 2 * H_);

    const int t   = threadIdx.x;
    const int dir = blockIdx.x >> 6;
    const int b   = blockIdx.x & 63;

    const float* W    = dir ? Whh_b : Whh_f;
    const float* xarr = dir ? g_xb  : g_xf;

    u64 wreg[KREGP];
#pragma unroll
    for (int p = 0; p < KREGP; p++)
        wreg[p] = pk2(W[(size_t)(2 * p) * H_ + t], W[(size_t)(2 * p + 1) * H_ + t]);
    for (int r = 0; r < KSH2; r++) {
        ulonglong2 w;
        w.x = pk2(W[(size_t)(2 * KREGP + 4 * r + 0) * H_ + t], W[(size_t)(2 * KREGP + 4 * r + 1) * H_ + t]);
        w.y = pk2(W[(size_t)(2 * KREGP + 4 * r + 2) * H_ + t], W[(size_t)(2 * KREGP + 4 * r + 3) * H_ + t]);
        Wsh2[r * H_ + t] = w;
    }
    h_sh[t] = 0.f;
    __syncthreads();

    const float* xp = xarr + (size_t)b * H_ + t;

    float* ghp = g_h + ((size_t)((dir ? (T_ - 1) : 0) * B_ + b)) * (2 * H_) + dir * H_ + t;
    const long long gstep = dir ? -(long long)(B_ * 2 * H_) : (long long)(B_ * 2 * H_);

    float xq[XPF];
#pragma unroll
    for (int i = 0; i < XPF; i++)
        xq[i] = (i < T_) ? xp[(size_t)i * (B_ * H_)] : 0.f;

    float hlast = 0.f;
    int p = 0;
    const u64 z2 = pk2(0.f, 0.f);

    for (int s = 0; s < T_; ++s) {
        u64 a0 = pk2(xq[0], 0.f), a1 = z2, a2 = z2, a3 = z2;
#pragma unroll
        for (int i = 0; i < XPF - 1; i++) xq[i] = xq[i + 1];
        if (s + XPF < T_) xq[XPF - 1] = xp[(size_t)(s + XPF) * (B_ * H_)];

        const ulonglong2* hc2 = (const ulonglong2*)(h_sh + p * H_);

#pragma unroll
        for (int q = 0; q < 2 * KREGP / 4; q++) {
            ulonglong2 hv = hc2[q];
            if (q & 1) {
                FMA2(a2, hv.x, wreg[2 * q + 0], a2);
                FMA2(a3, hv.y, wreg[2 * q + 1], a3);
            } else {
                FMA2(a0, hv.x, wreg[2 * q + 0], a0);
                FMA2(a1, hv.y, wreg[2 * q + 1], a1);
            }
        }
#pragma unroll
        for (int r = 0; r < KSH2; r++) {
            ulonglong2 hv = hc2[2 * KREGP / 4 + r];
            ulonglong2 wv = Wsh2[r * H_ + t];
            FMA2(a0, hv.x, wv.x, a0);
            FMA2(a1, hv.y, wv.y, a1);
        }

        float l0, u0, l1, u1, l2, u2, l3, u3;
        upk2(a0, l0, u0); upk2(a1, l1, u1);
        upk2(a2, l2, u2); upk2(a3, l3, u3);
        float sum = ((l0 + u0) + (l1 + u1)) + ((l2 + u2) + (l3 + u3));
        float hn = fast_tanh(sum);

        h_sh[(p ^ 1) * H_ + t] = hn;
        *ghp = hn;
        ghp += gstep;

        hlast = hn;
        p ^= 1;
        __syncthreads();
    }

    out[(size_t)B_ * T_ * O_ + (size_t)dir * (B_ * H_) + (size_t)b * H_ + t] = hlast;
}

// ---------------------------------------------------------------------------
// launch
// ---------------------------------------------------------------------------
extern "C" void kernel_launch(void* const* d_in, const int* in_sizes, int n_in,
                              void* d_out, int out_size)
{
    const float* X    = (const float*)d_in[0];
    const float* Wxhf = (const float*)d_in[1];
    const float* Whhf = (const float*)d_in[2];
    const float* bf   = (const float*)d_in[3];
    const float* Wxhb = (const float*)d_in[4];
    const float* Whhb = (const float*)d_in[5];
    const float* bb   = (const float*)d_in[6];
    const float* Why  = (const float*)d_in[7];
    const float* by   = (const float*)d_in[8];
    float* out = (float*)d_out;

    cudaFuncSetAttribute(scan_kernel,
                         cudaFuncAttributeMaxDynamicSharedMemorySize, (int)SMEM_SCAN);
    cudaFuncSetAttribute(proj_tc,
                         cudaFuncAttributeMaxDynamicSharedMemorySize, (int)SMEM_TC);
    cudaFuncSetAttribute(out_tc,
                         cudaFuncAttributeMaxDynamicSharedMemorySize, (int)SMEM_TC);

    setup_kernel<<<256, 256>>>(Wxhf, Wxhb, Why);
    proj_tc<<<dim3(M_ / 128, 2, 2), 256, SMEM_TC>>>(X, bf, bb);
    scan_kernel<<<128, 256, SMEM_SCAN>>>(Whhf, Whhb, out);
    out_tc<<<dim3(M_ / 128, 2), 256, SMEM_TC>>>(by, out);
}

// round 11
// speedup vs baseline: 1.2322x; 1.0390x over previous
#include <cuda_runtime.h>
#include <cuda_bf16.h>
#include <math.h>
#include <stdint.h>

// Problem dims (fixed)
#define B_  64
#define T_  512
#define E_  256
#define H_  256
#define O_  256
#define M_  (T_ * B_)          // 32768 rows

typedef unsigned long long u64;
typedef unsigned int u32;

// ---------------------------------------------------------------------------
// scan config (R8 winner, unchanged)
// ---------------------------------------------------------------------------
#define KREGP 100
#define KSH2  14
#define SMEM_SCAN ((2 * H_) * sizeof(float) + (KSH2 * H_) * sizeof(ulonglong2))
#define XPF 4

__device__ __forceinline__ u64 pk2(float lo, float hi) {
    u64 r;
    asm("mov.b64 %0, {%1, %2};" : "=l"(r) : "f"(lo), "f"(hi));
    return r;
}
__device__ __forceinline__ void upk2(u64 v, float& lo, float& hi) {
    asm("mov.b64 {%0, %1}, %2;" : "=f"(lo), "=f"(hi) : "l"(v));
}
#define FMA2(d, a, b, c) \
    asm("fma.rn.f32x2 %0, %1, %2, %3;" : "=l"(d) : "l"(a), "l"(b), "l"(c))

__device__ __forceinline__ float fast_tanh(float v) {
    float x = fminf(fmaxf(v, -15.f), 15.f);
    float e = __expf(2.f * x);
    return __fdividef(e - 1.f, e + 1.f);
}

// ---------------------------------------------------------------------------
// warp-mma + cp.async helpers (legacy path, works on bare sm_100 target)
// ---------------------------------------------------------------------------
__device__ __forceinline__ u32 smem_u32(const void* p) {
    u32 a;
    asm("{ .reg .u64 t; cvta.to.shared.u64 t, %1; cvt.u32.u64 %0, t; }" : "=r"(a) : "l"(p));
    return a;
}
#define LDSM_X4(r, addr) \
    asm volatile("ldmatrix.sync.aligned.m8n8.x4.shared.b16 {%0,%1,%2,%3}, [%4];" \
        : "=r"((r)[0]), "=r"((r)[1]), "=r"((r)[2]), "=r"((r)[3]) : "r"(addr))
#define MMA_BF16(c, a, b0, b1) \
    asm volatile("mma.sync.aligned.m16n8k16.row.col.f32.bf16.bf16.f32 " \
        "{%0,%1,%2,%3}, {%4,%5,%6,%7}, {%8,%9}, {%0,%1,%2,%3};" \
        : "+f"((c)[0]), "+f"((c)[1]), "+f"((c)[2]), "+f"((c)[3]) \
        : "r"((a)[0]), "r"((a)[1]), "r"((a)[2]), "r"((a)[3]), "r"(b0), "r"(b1))
#define CP16(dst, src) \
    asm volatile("cp.async.cg.shared.global [%0], [%1], 16;" :: "r"(dst), "l"(src))
#define CP_COMMIT()  asm volatile("cp.async.commit_group;" ::: "memory")
#define CP_WAIT1()   asm volatile("cp.async.wait_group 1;" ::: "memory")
#define CP_WAIT0()   asm volatile("cp.async.wait_group 0;" ::: "memory")

// ---------------------------------------------------------------------------
// Static device scratch
// ---------------------------------------------------------------------------
__device__ float g_xf[(size_t)T_ * B_ * H_];
__device__ float g_xb[(size_t)T_ * B_ * H_];
__device__ float g_h [(size_t)M_ * (2 * H_)];

// weights pre-split bf16 hi/lo, TRANSPOSED to [n][k] (k contiguous)
__device__ __nv_bfloat16 g_pBh[2 * H_ * E_];
__device__ __nv_bfloat16 g_pBl[2 * H_ * E_];
__device__ __nv_bfloat16 g_oBh[O_ * 2 * H_];
__device__ __nv_bfloat16 g_oBl[O_ * 2 * H_];

// ---------------------------------------------------------------------------
// GEMM smem: A (hi/lo, single) + B (hi/lo, DOUBLE buffered).
// rows padded to 144B -> LDSM conflict-free.
// ---------------------------------------------------------------------------
#define ROWB 144
#define SM_AH 0
#define SM_AL 18432
#define SM_B0 36864          // buffer stride 36864: BH at +0, BL at +18432
#define BBUF  36864
#define SMEM_TC (SM_B0 + 2 * BBUF)   // 110592

__device__ __forceinline__ unsigned pkbf(float a, float b) {
    unsigned lo = __bfloat16_as_ushort(__float2bfloat16_rn(a));
    unsigned hi = __bfloat16_as_ushort(__float2bfloat16_rn(b));
    return (hi << 16) | lo;
}
__device__ __forceinline__ void cvt8(const float* v, uint4& Hq, uint4& Lq) {
    float fh[8], fl[8];
#pragma unroll
    for (int i = 0; i < 8; i++) {
        __nv_bfloat16 h = __float2bfloat16_rn(v[i]);
        fh[i] = __bfloat162float(h);
        fl[i] = v[i] - fh[i];
    }
    Hq.x = pkbf(fh[0], fh[1]); Hq.y = pkbf(fh[2], fh[3]);
    Hq.z = pkbf(fh[4], fh[5]); Hq.w = pkbf(fh[6], fh[7]);
    Lq.x = pkbf(fl[0], fl[1]); Lq.y = pkbf(fl[2], fl[3]);
    Lq.z = pkbf(fl[4], fl[5]); Lq.w = pkbf(fl[6], fl[7]);
}

// ---------------------------------------------------------------------------
// setup: split + transpose weights
// ---------------------------------------------------------------------------
__global__ void setup_kernel(const float* __restrict__ Wf,
                             const float* __restrict__ Wb,
                             const float* __restrict__ Why)
{
    const int stride = gridDim.x * blockDim.x;
    for (int e = blockIdx.x * blockDim.x + threadIdx.x; e < E_ * H_; e += stride) {
        int k = e >> 8, n = e & 255;
        int idx = n * E_ + k;
        float wf = Wf[e], wb = Wb[e];
        __nv_bfloat16 hf = __float2bfloat16_rn(wf);
        __nv_bfloat16 hb = __float2bfloat16_rn(wb);
        g_pBh[idx] = hf;
        g_pBl[idx] = __float2bfloat16_rn(wf - __bfloat162float(hf));
        g_pBh[H_ * E_ + idx] = hb;
        g_pBl[H_ * E_ + idx] = __float2bfloat16_rn(wb - __bfloat162float(hb));
    }
    for (int e = blockIdx.x * blockDim.x + threadIdx.x; e < 2 * H_ * O_; e += stride) {
        int k = e >> 8, n = e & 255;
        int idx = n * (2 * H_) + k;
        float w = Why[e];
        __nv_bfloat16 h = __float2bfloat16_rn(w);
        g_oBh[idx] = h;
        g_oBl[idx] = __float2bfloat16_rn(w - __bfloat162float(h));
    }
}

// ---------------------------------------------------------------------------
// split-bf16 warp-MMA GEMM body, software-pipelined:
//  - B slabs via cp.async, double-buffered in smem (next slab lands during MMA)
//  - A slab registers prefetched one slab ahead
// C[128 x 128] block tile, K = NKT*64.
// ---------------------------------------------------------------------------
template <int NKT, int MODE>
__device__ __forceinline__ void gemm_mma_body(
    const float* __restrict__ Asrc,
    const __nv_bfloat16* __restrict__ Bh,
    const __nv_bfloat16* __restrict__ Bl,
    const float* __restrict__ bias,
    float* __restrict__ Cdst,
    int m0, int n0, int dir)
{
    extern __shared__ char smem[];
    const u32 smb = smem_u32(smem);
    const int tid = threadIdx.x;
    const int wid = tid >> 5;
    const int l   = tid & 31;
    const int wm  = wid & 1;
    const int wn  = wid >> 1;
    const int K   = NKT * 64;

    // A loader role: row r, k-half hf
    const int r  = tid >> 1;
    const int hf = tid & 1;
    const float* arow;
    {
        const int m = m0 + r;
        if (MODE == 0) {
            int t = m >> 6, b = m & 63;
            int xt = dir ? (T_ - 1 - t) : t;
            arow = Asrc + ((size_t)b * T_ + xt) * E_;
        } else {
            arow = Asrc + (size_t)m * (2 * H_);
        }
    }
    // B loader role: arr (hi/lo), row rb; 8 x 16B cp.async per slab
    const int barr = tid >> 7;
    const int rb   = tid & 127;
    const __nv_bfloat16* bsrc = (barr ? Bl : Bh) + (size_t)(n0 + rb) * K;
    const u32 bdst_off = (u32)(SM_B0 + (barr ? 18432 : 0) + rb * ROWB);

    // LDSM per-lane addresses (A absolute; B relative to buffer base)
    u32 aAH[4], aAL[4];
#pragma unroll
    for (int f = 0; f < 4; f++) {
        u32 off = (u32)((wm * 64 + 16 * f + (l & 15)) * ROWB + (l >> 4) * 16);
        aAH[f] = smb + SM_AH + off;
        aAL[f] = smb + SM_AL + off;
    }
    u32 bOff[2];
#pragma unroll
    for (int p = 0; p < 2; p++)
        bOff[p] = (u32)((wn * 32 + 16 * p + (l & 7) + (l >> 4) * 8) * ROWB + ((l >> 3) & 1) * 16);

    float cc[4][4][4];
#pragma unroll
    for (int f = 0; f < 4; f++)
#pragma unroll
        for (int g = 0; g < 4; g++)
#pragma unroll
            for (int i = 0; i < 4; i++) cc[f][g][i] = 0.f;

    // ---- prologue: B slab 0 via cp.async, A slab 0 into regs ----
#pragma unroll
    for (int i = 0; i < 8; i++)
        CP16(smb + bdst_off + i * 16, (const char*)(bsrc) + i * 16);
    CP_COMMIT();
    float av[32];
#pragma unroll
    for (int i = 0; i < 8; i++)
        *(float4*)&av[i * 4] = *(const float4*)(arow + hf * 32 + i * 4);

    for (int kt = 0; kt < NKT; kt++) {
        const int buf = kt & 1;

        if (kt > 0) __syncthreads();   // MMAs of kt-1 done: A smem + B buf free

        // store A (convert fp32 -> bf16 hi/lo) into smem
#pragma unroll
        for (int c = 0; c < 4; c++) {
            uint4 Hq, Lq;
            cvt8(&av[c * 8], Hq, Lq);
            int off = r * ROWB + hf * 64 + c * 16;
            *(uint4*)(smem + SM_AH + off) = Hq;
            *(uint4*)(smem + SM_AL + off) = Lq;
        }

        // issue B cp.async for next slab into the other buffer
        if (kt + 1 < NKT) {
            const u32 nb = smb + bdst_off + (1 - buf) * BBUF;
            const char* ns = (const char*)(bsrc + (kt + 1) * 64);
#pragma unroll
            for (int i = 0; i < 8; i++) CP16(nb + i * 16, ns + i * 16);
            CP_COMMIT();
            CP_WAIT1();                // B slab kt has landed
        } else {
            CP_WAIT0();
        }
        __syncthreads();               // A stores + B(kt) visible

        // prefetch A for next slab (global latency hidden under MMAs)
        if (kt + 1 < NKT) {
            const float* ap = arow + (kt + 1) * 64 + hf * 32;
#pragma unroll
            for (int i = 0; i < 8; i++)
                *(float4*)&av[i * 4] = *(const float4*)(ap + i * 4);
        }

        // 4 k-steps of 16
        const u32 bb = smb + buf * BBUF;
#pragma unroll
        for (int ks = 0; ks < 4; ks++) {
            const u32 kb = ks * 32;
            u32 ah[4][4], al[4][4], bh2[2][4], bl2[2][4];
#pragma unroll
            for (int f = 0; f < 4; f++) { LDSM_X4(ah[f], aAH[f] + kb); LDSM_X4(al[f], aAL[f] + kb); }
#pragma unroll
            for (int p = 0; p < 2; p++) {
                LDSM_X4(bh2[p], bb + SM_B0 + bOff[p] + kb);
                LDSM_X4(bl2[p], bb + SM_B0 + 18432 + bOff[p] + kb);
            }
#pragma unroll
            for (int f = 0; f < 4; f++)
#pragma unroll
                for (int g = 0; g < 4; g++) {
                    u32 h0 = bh2[g >> 1][(g & 1) * 2], h1 = bh2[g >> 1][(g & 1) * 2 + 1];
                    u32 l0 = bl2[g >> 1][(g & 1) * 2], l1 = bl2[g >> 1][(g & 1) * 2 + 1];
                    MMA_BF16(cc[f][g], ah[f], h0, h1);
                    MMA_BF16(cc[f][g], ah[f], l0, l1);
                    MMA_BF16(cc[f][g], al[f], h0, h1);
                }
        }
    }

    // epilogue
#pragma unroll
    for (int f = 0; f < 4; f++) {
        const int row0 = m0 + wm * 64 + 16 * f + (l >> 2);
#pragma unroll
        for (int g = 0; g < 4; g++) {
            const int col = n0 + wn * 32 + 8 * g + (l & 3) * 2;
            float2 bv = *(const float2*)(bias + col);
            float2 v0 = { cc[f][g][0] + bv.x, cc[f][g][1] + bv.y };
            float2 v1 = { cc[f][g][2] + bv.x, cc[f][g][3] + bv.y };
            if (MODE == 0) {
                *(float2*)(Cdst + (size_t)row0 * H_ + col) = v0;
                *(float2*)(Cdst + (size_t)(row0 + 8) * H_ + col) = v1;
            } else {
                int t0 = row0 >> 6, b0 = row0 & 63;
                int t1 = (row0 + 8) >> 6, b1 = (row0 + 8) & 63;
                *(float2*)(Cdst + ((size_t)b0 * T_ + t0) * O_ + col) = v0;
                *(float2*)(Cdst + ((size_t)b1 * T_ + t1) * O_ + col) = v1;
            }
        }
    }
}

__global__ __launch_bounds__(256, 1) void proj_tc(
    const float* __restrict__ X,
    const float* __restrict__ bfv, const float* __restrict__ bbv)
{
    const int dir = blockIdx.z;
    gemm_mma_body<4, 0>(X,
                        g_pBh + dir * (H_ * E_), g_pBl + dir * (H_ * E_),
                        dir ? bbv : bfv,
                        dir ? g_xb : g_xf,
                        blockIdx.x * 128, blockIdx.y * 128, dir);
}

__global__ __launch_bounds__(256, 1) void out_tc(
    const float* __restrict__ byv, float* __restrict__ out)
{
    gemm_mma_body<8, 1>(g_h, g_oBh, g_oBl, byv, out,
                        blockIdx.x * 128, blockIdx.y * 128, 0);
}

// ---------------------------------------------------------------------------
// scan kernel — EXACT R8 winner
// ---------------------------------------------------------------------------
extern __shared__ float smem_scan[];

__global__ __launch_bounds__(256) void scan_kernel(
    const float* __restrict__ Whh_f,
    const float* __restrict__ Whh_b,
    float* __restrict__ out)
{
    float*      h_sh = smem_scan;
    ulonglong2* Wsh2 = (ulonglong2*)(smem_scan + 2 * H_);

    const int t   = threadIdx.x;
    const int dir = blockIdx.x >> 6;
    const int b   = blockIdx.x & 63;

    const float* W    = dir ? Whh_b : Whh_f;
    const float* xarr = dir ? g_xb  : g_xf;

    u64 wreg[KREGP];
#pragma unroll
    for (int p = 0; p < KREGP; p++)
        wreg[p] = pk2(W[(size_t)(2 * p) * H_ + t], W[(size_t)(2 * p + 1) * H_ + t]);
    for (int r = 0; r < KSH2; r++) {
        ulonglong2 w;
        w.x = pk2(W[(size_t)(2 * KREGP + 4 * r + 0) * H_ + t], W[(size_t)(2 * KREGP + 4 * r + 1) * H_ + t]);
        w.y = pk2(W[(size_t)(2 * KREGP + 4 * r + 2) * H_ + t], W[(size_t)(2 * KREGP + 4 * r + 3) * H_ + t]);
        Wsh2[r * H_ + t] = w;
    }
    h_sh[t] = 0.f;
    __syncthreads();

    const float* xp = xarr + (size_t)b * H_ + t;

    float* ghp = g_h + ((size_t)((dir ? (T_ - 1) : 0) * B_ + b)) * (2 * H_) + dir * H_ + t;
    const long long gstep = dir ? -(long long)(B_ * 2 * H_) : (long long)(B_ * 2 * H_);

    float xq[XPF];
#pragma unroll
    for (int i = 0; i < XPF; i++)
        xq[i] = (i < T_) ? xp[(size_t)i * (B_ * H_)] : 0.f;

    float hlast = 0.f;
    int p = 0;
    const u64 z2 = pk2(0.f, 0.f);

    for (int s = 0; s < T_; ++s) {
        u64 a0 = pk2(xq[0], 0.f), a1 = z2, a2 = z2, a3 = z2;
#pragma unroll
        for (int i = 0; i < XPF - 1; i++) xq[i] = xq[i + 1];
        if (s + XPF < T_) xq[XPF - 1] = xp[(size_t)(s + XPF) * (B_ * H_)];

        const ulonglong2* hc2 = (const ulonglong2*)(h_sh + p * H_);

#pragma unroll
        for (int q = 0; q < 2 * KREGP / 4; q++) {
            ulonglong2 hv = hc2[q];
            if (q & 1) {
                FMA2(a2, hv.x, wreg[2 * q + 0], a2);
                FMA2(a3, hv.y, wreg[2 * q + 1], a3);
            } else {
                FMA2(a0, hv.x, wreg[2 * q + 0], a0);
                FMA2(a1, hv.y, wreg[2 * q + 1], a1);
            }
        }
#pragma unroll
        for (int r = 0; r < KSH2; r++) {
            ulonglong2 hv = hc2[2 * KREGP / 4 + r];
            ulonglong2 wv = Wsh2[r * H_ + t];
            FMA2(a0, hv.x, wv.x, a0);
            FMA2(a1, hv.y, wv.y, a1);
        }

        float l0, u0, l1, u1, l2, u2, l3, u3;
        upk2(a0, l0, u0); upk2(a1, l1, u1);
        upk2(a2, l2, u2); upk2(a3, l3, u3);
        float sum = ((l0 + u0) + (l1 + u1)) + ((l2 + u2) + (l3 + u3));
        float hn = fast_tanh(sum);

        h_sh[(p ^ 1) * H_ + t] = hn;
        *ghp = hn;
        ghp += gstep;

        hlast = hn;
        p ^= 1;
        __syncthreads();
    }

    out[(size_t)B_ * T_ * O_ + (size_t)dir * (B_ * H_) + (size_t)b * H_ + t] = hlast;
}

// ---------------------------------------------------------------------------
// launch
// ---------------------------------------------------------------------------
extern "C" void kernel_launch(void* const* d_in, const int* in_sizes, int n_in,
                              void* d_out, int out_size)
{
    const float* X    = (const float*)d_in[0];
    const float* Wxhf = (const float*)d_in[1];
    const float* Whhf = (const float*)d_in[2];
    const float* bf   = (const float*)d_in[3];
    const float* Wxhb = (const float*)d_in[4];
    const float* Whhb = (const float*)d_in[5];
    const float* bb   = (const float*)d_in[6];
    const float* Why  = (const float*)d_in[7];
    const float* by   = (const float*)d_in[8];
    float* out = (float*)d_out;

    cudaFuncSetAttribute(scan_kernel,
                         cudaFuncAttributeMaxDynamicSharedMemorySize, (int)SMEM_SCAN);
    cudaFuncSetAttribute(proj_tc,
                         cudaFuncAttributeMaxDynamicSharedMemorySize, (int)SMEM_TC);
    cudaFuncSetAttribute(out_tc,
                         cudaFuncAttributeMaxDynamicSharedMemorySize, (int)SMEM_TC);

    setup_kernel<<<256, 256>>>(Wxhf, Wxhb, Why);
    proj_tc<<<dim3(M_ / 128, 2, 2), 256, SMEM_TC>>>(X, bf, bb);
    scan_kernel<<<128, 256, SMEM_SCAN>>>(Whhf, Whhb, out);
    out_tc<<<dim3(M_ / 128, 2), 256, SMEM_TC>>>(by, out);
}

// round 12
// speedup vs baseline: 1.2513x; 1.0155x over previous
#include <cuda_runtime.h>
#include <cuda_bf16.h>
#include <math.h>
#include <stdint.h>

// Problem dims (fixed)
#define B_  64
#define T_  512
#define E_  256
#define H_  256
#define O_  256
#define M_  (T_ * B_)          // 32768 rows

typedef unsigned long long u64;
typedef unsigned int u32;

// ---------------------------------------------------------------------------
// scan config (R8 winner, unchanged)
// ---------------------------------------------------------------------------
#define KREGP 100
#define KSH2  14
#define SMEM_SCAN ((2 * H_) * sizeof(float) + (KSH2 * H_) * sizeof(ulonglong2))
#define XPF 4

__device__ __forceinline__ u64 pk2(float lo, float hi) {
    u64 r;
    asm("mov.b64 %0, {%1, %2};" : "=l"(r) : "f"(lo), "f"(hi));
    return r;
}
__device__ __forceinline__ void upk2(u64 v, float& lo, float& hi) {
    asm("mov.b64 {%0, %1}, %2;" : "=f"(lo), "=f"(hi) : "l"(v));
}
#define FMA2(d, a, b, c) \
    asm("fma.rn.f32x2 %0, %1, %2, %3;" : "=l"(d) : "l"(a), "l"(b), "l"(c))

__device__ __forceinline__ float fast_tanh(float v) {
    float x = fminf(fmaxf(v, -15.f), 15.f);
    float e = __expf(2.f * x);
    return __fdividef(e - 1.f, e + 1.f);
}

// ---------------------------------------------------------------------------
// warp-mma + cp.async helpers
// ---------------------------------------------------------------------------
__device__ __forceinline__ u32 smem_u32(const void* p) {
    u32 a;
    asm("{ .reg .u64 t; cvta.to.shared.u64 t, %1; cvt.u32.u64 %0, t; }" : "=r"(a) : "l"(p));
    return a;
}
#define LDSM_X4(r, addr) \
    asm volatile("ldmatrix.sync.aligned.m8n8.x4.shared.b16 {%0,%1,%2,%3}, [%4];" \
        : "=r"((r)[0]), "=r"((r)[1]), "=r"((r)[2]), "=r"((r)[3]) : "r"(addr))
#define MMA_BF16(c, a, b0, b1) \
    asm volatile("mma.sync.aligned.m16n8k16.row.col.f32.bf16.bf16.f32 " \
        "{%0,%1,%2,%3}, {%4,%5,%6,%7}, {%8,%9}, {%0,%1,%2,%3};" \
        : "+f"((c)[0]), "+f"((c)[1]), "+f"((c)[2]), "+f"((c)[3]) \
        : "r"((a)[0]), "r"((a)[1]), "r"((a)[2]), "r"((a)[3]), "r"(b0), "r"(b1))
#define CP16(dst, src) \
    asm volatile("cp.async.cg.shared.global [%0], [%1], 16;" :: "r"(dst), "l"(src))
#define CP_COMMIT()  asm volatile("cp.async.commit_group;" ::: "memory")
#define CP_WAIT1()   asm volatile("cp.async.wait_group 1;" ::: "memory")
#define CP_WAIT0()   asm volatile("cp.async.wait_group 0;" ::: "memory")

// ---------------------------------------------------------------------------
// Static device scratch
// ---------------------------------------------------------------------------
__device__ float g_xf[(size_t)T_ * B_ * H_];
__device__ float g_xb[(size_t)T_ * B_ * H_];
__device__ float g_h [(size_t)M_ * (2 * H_)];

// weights pre-split bf16 hi/lo, TRANSPOSED to [n][k] (k contiguous)
__device__ __nv_bfloat16 g_pBh[2 * H_ * E_];
__device__ __nv_bfloat16 g_pBl[2 * H_ * E_];
__device__ __nv_bfloat16 g_oBh[O_ * 2 * H_];
__device__ __nv_bfloat16 g_oBl[O_ * 2 * H_];

// ---------------------------------------------------------------------------
// GEMM smem (128x64 tile): A (hi/lo, single) + B (hi/lo, DOUBLE buffered).
// rows padded to 144B -> LDSM conflict-free. 72KB/CTA -> 2 CTAs/SM.
// ---------------------------------------------------------------------------
#define ROWB 144
#define SM_AH 0
#define SM_AL 18432
#define SM_B0 36864          // per buffer: BH at +0 (9216), BL at +9216
#define BBUF  18432
#define SMEM_TC (SM_B0 + 2 * BBUF)   // 73728

__device__ __forceinline__ unsigned pkbf(float a, float b) {
    unsigned lo = __bfloat16_as_ushort(__float2bfloat16_rn(a));
    unsigned hi = __bfloat16_as_ushort(__float2bfloat16_rn(b));
    return (hi << 16) | lo;
}
__device__ __forceinline__ void cvt8(const float* v, uint4& Hq, uint4& Lq) {
    float fh[8], fl[8];
#pragma unroll
    for (int i = 0; i < 8; i++) {
        __nv_bfloat16 h = __float2bfloat16_rn(v[i]);
        fh[i] = __bfloat162float(h);
        fl[i] = v[i] - fh[i];
    }
    Hq.x = pkbf(fh[0], fh[1]); Hq.y = pkbf(fh[2], fh[3]);
    Hq.z = pkbf(fh[4], fh[5]); Hq.w = pkbf(fh[6], fh[7]);
    Lq.x = pkbf(fl[0], fl[1]); Lq.y = pkbf(fl[2], fl[3]);
    Lq.z = pkbf(fl[4], fl[5]); Lq.w = pkbf(fl[6], fl[7]);
}

// ---------------------------------------------------------------------------
// setup: split + transpose weights
// ---------------------------------------------------------------------------
__global__ void setup_kernel(const float* __restrict__ Wf,
                             const float* __restrict__ Wb,
                             const float* __restrict__ Why)
{
    const int stride = gridDim.x * blockDim.x;
    for (int e = blockIdx.x * blockDim.x + threadIdx.x; e < E_ * H_; e += stride) {
        int k = e >> 8, n = e & 255;
        int idx = n * E_ + k;
        float wf = Wf[e], wb = Wb[e];
        __nv_bfloat16 hf = __float2bfloat16_rn(wf);
        __nv_bfloat16 hb = __float2bfloat16_rn(wb);
        g_pBh[idx] = hf;
        g_pBl[idx] = __float2bfloat16_rn(wf - __bfloat162float(hf));
        g_pBh[H_ * E_ + idx] = hb;
        g_pBl[H_ * E_ + idx] = __float2bfloat16_rn(wb - __bfloat162float(hb));
    }
    for (int e = blockIdx.x * blockDim.x + threadIdx.x; e < 2 * H_ * O_; e += stride) {
        int k = e >> 8, n = e & 255;
        int idx = n * (2 * H_) + k;
        float w = Why[e];
        __nv_bfloat16 h = __float2bfloat16_rn(w);
        g_oBh[idx] = h;
        g_oBl[idx] = __float2bfloat16_rn(w - __bfloat162float(h));
    }
}

// ---------------------------------------------------------------------------
// split-bf16 warp-MMA GEMM body, pipelined, 128(M) x 64(N) tile, K = NKT*64.
// 8 warps as 4(M) x 2(N); warp tile 32x32.
// ---------------------------------------------------------------------------
template <int NKT, int MODE>
__device__ __forceinline__ void gemm_mma_body(
    const float* __restrict__ Asrc,
    const __nv_bfloat16* __restrict__ Bh,
    const __nv_bfloat16* __restrict__ Bl,
    const float* __restrict__ bias,
    float* __restrict__ Cdst,
    int m0, int n0, int dir)
{
    extern __shared__ char smem[];
    const u32 smb = smem_u32(smem);
    const int tid = threadIdx.x;
    const int wid = tid >> 5;
    const int l   = tid & 31;
    const int wm  = wid & 3;       // 4 warp-rows of 32
    const int wn  = wid >> 2;      // 2 warp-cols of 32
    const int K   = NKT * 64;

    // A loader role: row r, k-half hf
    const int r  = tid >> 1;
    const int hf = tid & 1;
    const float* arow;
    {
        const int m = m0 + r;
        if (MODE == 0) {
            int t = m >> 6, b = m & 63;
            int xt = dir ? (T_ - 1 - t) : t;
            arow = Asrc + ((size_t)b * T_ + xt) * E_;
        } else {
            arow = Asrc + (size_t)m * (2 * H_);
        }
    }
    // B loader role: slot = (arr, row), 2 threads per slot (64B halves)
    const int slot  = tid >> 1;           // 0..127
    const int bhalf = tid & 1;
    const int barr  = slot >> 6;          // 0 = hi, 1 = lo
    const int rb    = slot & 63;
    const __nv_bfloat16* bsrc = (barr ? Bl : Bh) + (size_t)(n0 + rb) * K + bhalf * 32;
    const u32 bdst_off = (u32)(SM_B0 + barr * 9216 + rb * ROWB + bhalf * 64);

    // LDSM per-lane addresses
    u32 aAH[2], aAL[2];
#pragma unroll
    for (int f = 0; f < 2; f++) {
        u32 off = (u32)((wm * 32 + 16 * f + (l & 15)) * ROWB + (l >> 4) * 16);
        aAH[f] = smb + SM_AH + off;
        aAL[f] = smb + SM_AL + off;
    }
    u32 bOff[2];
#pragma unroll
    for (int p = 0; p < 2; p++)
        bOff[p] = (u32)((wn * 32 + 16 * p + (l & 7) + (l >> 4) * 8) * ROWB + ((l >> 3) & 1) * 16);

    float cc[2][4][4];
#pragma unroll
    for (int f = 0; f < 2; f++)
#pragma unroll
        for (int g = 0; g < 4; g++)
#pragma unroll
            for (int i = 0; i < 4; i++) cc[f][g][i] = 0.f;

    // ---- prologue ----
#pragma unroll
    for (int i = 0; i < 4; i++)
        CP16(smb + bdst_off + i * 16, (const char*)(bsrc) + i * 16);
    CP_COMMIT();
    float av[32];
#pragma unroll
    for (int i = 0; i < 8; i++)
        *(float4*)&av[i * 4] = *(const float4*)(arow + hf * 32 + i * 4);

    for (int kt = 0; kt < NKT; kt++) {
        const int buf = kt & 1;

        if (kt > 0) __syncthreads();

        // store A (convert fp32 -> bf16 hi/lo) into smem
#pragma unroll
        for (int c = 0; c < 4; c++) {
            uint4 Hq, Lq;
            cvt8(&av[c * 8], Hq, Lq);
            int off = r * ROWB + hf * 64 + c * 16;
            *(uint4*)(smem + SM_AH + off) = Hq;
            *(uint4*)(smem + SM_AL + off) = Lq;
        }

        // B cp.async for next slab into the other buffer
        if (kt + 1 < NKT) {
            const u32 nb = smb + bdst_off + (1 - buf) * BBUF;
            const char* ns = (const char*)(bsrc + (kt + 1) * 64);
#pragma unroll
            for (int i = 0; i < 4; i++) CP16(nb + i * 16, ns + i * 16);
            CP_COMMIT();
            CP_WAIT1();
        } else {
            CP_WAIT0();
        }
        __syncthreads();

        // prefetch A for next slab
        if (kt + 1 < NKT) {
            const float* ap = arow + (kt + 1) * 64 + hf * 32;
#pragma unroll
            for (int i = 0; i < 8; i++)
                *(float4*)&av[i * 4] = *(const float4*)(ap + i * 4);
        }

        // 4 k-steps of 16
        const u32 bb = smb + buf * BBUF;
#pragma unroll
        for (int ks = 0; ks < 4; ks++) {
            const u32 kb = ks * 32;
            u32 ah[2][4], al[2][4], bh2[2][4], bl2[2][4];
#pragma unroll
            for (int f = 0; f < 2; f++) { LDSM_X4(ah[f], aAH[f] + kb); LDSM_X4(al[f], aAL[f] + kb); }
#pragma unroll
            for (int p = 0; p < 2; p++) {
                LDSM_X4(bh2[p], bb + SM_B0 + bOff[p] + kb);
                LDSM_X4(bl2[p], bb + SM_B0 + 9216 + bOff[p] + kb);
            }
#pragma unroll
            for (int f = 0; f < 2; f++)
#pragma unroll
                for (int g = 0; g < 4; g++) {
                    u32 h0 = bh2[g >> 1][(g & 1) * 2], h1 = bh2[g >> 1][(g & 1) * 2 + 1];
                    u32 l0 = bl2[g >> 1][(g & 1) * 2], l1 = bl2[g >> 1][(g & 1) * 2 + 1];
                    MMA_BF16(cc[f][g], ah[f], h0, h1);
                    MMA_BF16(cc[f][g], ah[f], l0, l1);
                    MMA_BF16(cc[f][g], al[f], h0, h1);
                }
        }
    }

    // epilogue
#pragma unroll
    for (int f = 0; f < 2; f++) {
        const int row0 = m0 + wm * 32 + 16 * f + (l >> 2);
#pragma unroll
        for (int g = 0; g < 4; g++) {
            const int col = n0 + wn * 32 + 8 * g + (l & 3) * 2;
            float2 bv = *(const float2*)(bias + col);
            float2 v0 = { cc[f][g][0] + bv.x, cc[f][g][1] + bv.y };
            float2 v1 = { cc[f][g][2] + bv.x, cc[f][g][3] + bv.y };
            if (MODE == 0) {
                *(float2*)(Cdst + (size_t)row0 * H_ + col) = v0;
                *(float2*)(Cdst + (size_t)(row0 + 8) * H_ + col) = v1;
            } else {
                int t0 = row0 >> 6, b0 = row0 & 63;
                int t1 = (row0 + 8) >> 6, b1 = (row0 + 8) & 63;
                *(float2*)(Cdst + ((size_t)b0 * T_ + t0) * O_ + col) = v0;
                *(float2*)(Cdst + ((size_t)b1 * T_ + t1) * O_ + col) = v1;
            }
        }
    }
}

__global__ __launch_bounds__(256, 2) void proj_tc(
    const float* __restrict__ X,
    const float* __restrict__ bfv, const float* __restrict__ bbv)
{
    const int dir = blockIdx.z;
    gemm_mma_body<4, 0>(X,
                        g_pBh + dir * (H_ * E_), g_pBl + dir * (H_ * E_),
                        dir ? bbv : bfv,
                        dir ? g_xb : g_xf,
                        blockIdx.x * 128, blockIdx.y * 64, dir);
}

__global__ __launch_bounds__(256, 2) void out_tc(
    const float* __restrict__ byv, float* __restrict__ out)
{
    gemm_mma_body<8, 1>(g_h, g_oBh, g_oBl, byv, out,
                        blockIdx.x * 128, blockIdx.y * 64, 0);
}

// ---------------------------------------------------------------------------
// scan kernel — EXACT R8 winner
// ---------------------------------------------------------------------------
extern __shared__ float smem_scan[];

__global__ __launch_bounds__(256) void scan_kernel(
    const float* __restrict__ Whh_f,
    const float* __restrict__ Whh_b,
    float* __restrict__ out)
{
    float*      h_sh = smem_scan;
    ulonglong2* Wsh2 = (ulonglong2*)(smem_scan + 2 * H_);

    const int t   = threadIdx.x;
    const int dir = blockIdx.x >> 6;
    const int b   = blockIdx.x & 63;

    const float* W    = dir ? Whh_b : Whh_f;
    const float* xarr = dir ? g_xb  : g_xf;

    u64 wreg[KREGP];
#pragma unroll
    for (int p = 0; p < KREGP; p++)
        wreg[p] = pk2(W[(size_t)(2 * p) * H_ + t], W[(size_t)(2 * p + 1) * H_ + t]);
    for (int r = 0; r < KSH2; r++) {
        ulonglong2 w;
        w.x = pk2(W[(size_t)(2 * KREGP + 4 * r + 0) * H_ + t], W[(size_t)(2 * KREGP + 4 * r + 1) * H_ + t]);
        w.y = pk2(W[(size_t)(2 * KREGP + 4 * r + 2) * H_ + t], W[(size_t)(2 * KREGP + 4 * r + 3) * H_ + t]);
        Wsh2[r * H_ + t] = w;
    }
    h_sh[t] = 0.f;
    __syncthreads();

    const float* xp = xarr + (size_t)b * H_ + t;

    float* ghp = g_h + ((size_t)((dir ? (T_ - 1) : 0) * B_ + b)) * (2 * H_) + dir * H_ + t;
    const long long gstep = dir ? -(long long)(B_ * 2 * H_) : (long long)(B_ * 2 * H_);

    float xq[XPF];
#pragma unroll
    for (int i = 0; i < XPF; i++)
        xq[i] = (i < T_) ? xp[(size_t)i * (B_ * H_)] : 0.f;

    float hlast = 0.f;
    int p = 0;
    const u64 z2 = pk2(0.f, 0.f);

    for (int s = 0; s < T_; ++s) {
        u64 a0 = pk2(xq[0], 0.f), a1 = z2, a2 = z2, a3 = z2;
#pragma unroll
        for (int i = 0; i < XPF - 1; i++) xq[i] = xq[i + 1];
        if (s + XPF < T_) xq[XPF - 1] = xp[(size_t)(s + XPF) * (B_ * H_)];

        const ulonglong2* hc2 = (const ulonglong2*)(h_sh + p * H_);

#pragma unroll
        for (int q = 0; q < 2 * KREGP / 4; q++) {
            ulonglong2 hv = hc2[q];
            if (q & 1) {
                FMA2(a2, hv.x, wreg[2 * q + 0], a2);
                FMA2(a3, hv.y, wreg[2 * q + 1], a3);
            } else {
                FMA2(a0, hv.x, wreg[2 * q + 0], a0);
                FMA2(a1, hv.y, wreg[2 * q + 1], a1);
            }
        }
#pragma unroll
        for (int r = 0; r < KSH2; r++) {
            ulonglong2 hv = hc2[2 * KREGP / 4 + r];
            ulonglong2 wv = Wsh2[r * H_ + t];
            FMA2(a0, hv.x, wv.x, a0);
            FMA2(a1, hv.y, wv.y, a1);
        }

        float l0, u0, l1, u1, l2, u2, l3, u3;
        upk2(a0, l0, u0); upk2(a1, l1, u1);
        upk2(a2, l2, u2); upk2(a3, l3, u3);
        float sum = ((l0 + u0) + (l1 + u1)) + ((l2 + u2) + (l3 + u3));
        float hn = fast_tanh(sum);

        h_sh[(p ^ 1) * H_ + t] = hn;
        *ghp = hn;
        ghp += gstep;

        hlast = hn;
        p ^= 1;
        __syncthreads();
    }

    out[(size_t)B_ * T_ * O_ + (size_t)dir * (B_ * H_) + (size_t)b * H_ + t] = hlast;
}

// ---------------------------------------------------------------------------
// launch
// ---------------------------------------------------------------------------
extern "C" void kernel_launch(void* const* d_in, const int* in_sizes, int n_in,
                              void* d_out, int out_size)
{
    const float* X    = (const float*)d_in[0];
    const float* Wxhf = (const float*)d_in[1];
    const float* Whhf = (const float*)d_in[2];
    const float* bf   = (const float*)d_in[3];
    const float* Wxhb = (const float*)d_in[4];
    const float* Whhb = (const float*)d_in[5];
    const float* bb   = (const float*)d_in[6];
    const float* Why  = (const float*)d_in[7];
    const float* by   = (const float*)d_in[8];
    float* out = (float*)d_out;

    cudaFuncSetAttribute(scan_kernel,
                         cudaFuncAttributeMaxDynamicSharedMemorySize, (int)SMEM_SCAN);
    cudaFuncSetAttribute(proj_tc,
                         cudaFuncAttributeMaxDynamicSharedMemorySize, (int)SMEM_TC);
    cudaFuncSetAttribute(out_tc,
                         cudaFuncAttributeMaxDynamicSharedMemorySize, (int)SMEM_TC);

    setup_kernel<<<256, 256>>>(Wxhf, Wxhb, Why);
    proj_tc<<<dim3(M_ / 128, H_ / 64, 2), 256, SMEM_TC>>>(X, bf, bb);
    scan_kernel<<<128, 256, SMEM_SCAN>>>(Whhf, Whhb, out);
    out_tc<<<dim3(M_ / 128, O_ / 64), 256, SMEM_TC>>>(by, out);
}